// round 6
// baseline (speedup 1.0000x reference)
#include <cuda_runtime.h>
#include <cuda_bf16.h>
#include <cstdint>

// ---------------------------------------------------------------------------
// LastAggregator: out[n, :] = msg[argmax_{i : index[i]==n} t[i], :]
// (ties -> smallest i; empty segments -> zeros)
//
//   key(i) = (total_order(t[i]) << 32) | ~i    packed into u64
//   atomicMax over keys per segment  ->  winner = ~(low 32 bits)
//   key == 0  <=>  empty segment (valid keys have nonzero low word).
//
// Self-cleaning: the gather kernel resets each consumed key to 0, so no
// separate init pass is needed (device globals start zero-initialized,
// and every call leaves the array cleared -> identical work per call).
//
// index arrives as int32 (JAX x64 disabled downcasts the declared int64).
// ---------------------------------------------------------------------------

#define MAX_SEGMENTS (1 << 17)  // 131072 >= N = 65536
__device__ unsigned long long g_key[MAX_SEGMENTS];

__device__ __forceinline__ void stcs_f4(float4* p, float4 v) {
    // streaming store: don't let write-once output evict winner rows from L2
    asm volatile("st.global.cs.v4.f32 [%0], {%1,%2,%3,%4};"
                 :: "l"(p), "f"(v.x), "f"(v.y), "f"(v.z), "f"(v.w) : "memory");
}

__device__ __forceinline__ unsigned long long
make_key(float tv, unsigned int i) {
    unsigned int fb  = __float_as_uint(tv);
    unsigned int ord = (fb & 0x80000000u) ? ~fb : (fb | 0x80000000u);
    return ((unsigned long long)ord << 32) | (unsigned long long)(~i);
}

// --- argmax: 4 events per thread, vectorized loads --------------------------
__global__ void la_argmax_kernel(const int* __restrict__ index,
                                 const float* __restrict__ t,
                                 int M, int N) {
    int base = (blockIdx.x * blockDim.x + threadIdx.x) * 4;
    if (base + 3 < M) {
        int4   s  = *reinterpret_cast<const int4*>(index + base);
        float4 tv = *reinterpret_cast<const float4*>(t + base);
        int   segs[4] = {s.x, s.y, s.z, s.w};
        float ts[4]   = {tv.x, tv.y, tv.z, tv.w};
#pragma unroll
        for (int k = 0; k < 4; ++k) {
            unsigned long long key = make_key(ts[k], (unsigned int)(base + k));
            int seg = segs[k];
            if (seg >= 0 && seg < N) atomicMax(&g_key[seg], key);  // -> REDG
        }
    } else {
        for (int i = base; i < M; ++i) {
            unsigned long long key = make_key(t[i], (unsigned int)i);
            int seg = index[i];
            if (seg >= 0 && seg < N) atomicMax(&g_key[seg], key);
        }
    }
}

// --- D=256 gather: one warp per 4 rows; self-cleans keys --------------------
// Each thread carries 4 independent key->data chains: 8 LDG.128 + 8 STG.128.
__global__ void la_gather_d256_kernel(const float4* __restrict__ msg,
                                      float4* __restrict__ out,
                                      int N) {
    int gwarp = (blockIdx.x * blockDim.x + threadIdx.x) >> 5;
    int lane  = threadIdx.x & 31;
    int r0 = gwarp * 4;
    if (r0 >= N) return;

    // lanes 0..3 fetch the four keys in parallel
    unsigned long long kk = 0ull;
    if (lane < 4 && (r0 + lane) < N) kk = g_key[r0 + lane];

    unsigned long long key[4];
#pragma unroll
    for (int j = 0; j < 4; ++j)
        key[j] = __shfl_sync(0xffffffffu, kk, j);

    // self-clean for next call (all lanes hold values now)
    if (lane < 4 && (r0 + lane) < N) g_key[r0 + lane] = 0ull;

    const float4 z = make_float4(0.f, 0.f, 0.f, 0.f);
    float4 v[4][2];

    // issue all loads first: 8 independent LDG.128
#pragma unroll
    for (int j = 0; j < 4; ++j) {
        v[j][0] = z; v[j][1] = z;
        if ((r0 + j) < N && key[j] != 0ull) {
            size_t ib = (size_t)(~(unsigned int)(key[j] & 0xFFFFFFFFull)) * 64;
            v[j][0] = __ldg(&msg[ib + lane]);
            v[j][1] = __ldg(&msg[ib + lane + 32]);
        }
    }

    // then all stores
#pragma unroll
    for (int j = 0; j < 4; ++j) {
        if ((r0 + j) < N) {
            size_t ob = (size_t)(r0 + j) * 64;
            stcs_f4(&out[ob + lane],      v[j][0]);
            stcs_f4(&out[ob + lane + 32], v[j][1]);
        }
    }
}

// --- generic fallback (unexpected D): init + argmax + gather ----------------
__global__ void la_init_kernel(int N) {
    int i = blockIdx.x * blockDim.x + threadIdx.x;
    if (i < N) g_key[i] = 0ull;
}

__global__ void la_gather_generic_kernel(const float4* __restrict__ msg,
                                         float4* __restrict__ out,
                                         int N, int D4) {
    long long e = (long long)blockIdx.x * blockDim.x + threadIdx.x;
    long long total = (long long)N * D4;
    if (e >= total) return;
    int row  = (int)(e / D4);
    int lane = (int)(e % D4);
    unsigned long long key = g_key[row];
    float4 v = make_float4(0.f, 0.f, 0.f, 0.f);
    if (key != 0ull) {
        unsigned int win = ~(unsigned int)(key & 0xFFFFFFFFull);
        v = __ldg(&msg[(size_t)win * D4 + lane]);
    }
    out[(size_t)row * D4 + lane] = v;
}

extern "C" void kernel_launch(void* const* d_in, const int* in_sizes, int n_in,
                              void* d_out, int out_size) {
    // metadata order: msg [M*D f32], index [M i32], t [M f32], (dim_size)
    const float* msg   = (const float*)d_in[0];
    const int*   index = (const int*)d_in[1];
    const float* t     = (const float*)d_in[2];
    float*       out   = (float*)d_out;

    int M = in_sizes[1];              // 262144
    int D = in_sizes[0] / M;          // 256
    int N = out_size / D;             // 65536
    if (N > MAX_SEGMENTS) N = MAX_SEGMENTS;

    if (D == 256) {
        {   // argmax: 4 events/thread -> 256 blocks
            int threads = 256;
            int per_blk = threads * 4;
            int blocks  = (M + per_blk - 1) / per_blk;
            la_argmax_kernel<<<blocks, threads>>>(index, t, M, N);
        }
        {   // gather: 4 rows per warp, self-cleaning
            int threads = 256;                     // 8 warps = 32 rows/block
            int rows_per_blk = (threads / 32) * 4;
            int blocks = (N + rows_per_blk - 1) / rows_per_blk;
            la_gather_d256_kernel<<<blocks, threads>>>((const float4*)msg,
                                                       (float4*)out, N);
        }
    } else {
        // generic safe path
        {
            int threads = 256;
            int blocks  = (N + threads - 1) / threads;
            la_init_kernel<<<blocks, threads>>>(N);
        }
        {
            int threads = 256;
            int per_blk = threads * 4;
            int blocks  = (M + per_blk - 1) / per_blk;
            la_argmax_kernel<<<blocks, threads>>>(index, t, M, N);
        }
        {
            int D4 = D / 4;
            long long total = (long long)N * D4;
            int threads = 256;
            int blocks  = (int)((total + threads - 1) / threads);
            la_gather_generic_kernel<<<blocks, threads>>>((const float4*)msg,
                                                          (float4*)out, N, D4);
        }
    }
}